// round 8
// baseline (speedup 1.0000x reference)
#include <cuda_runtime.h>

// Problem constants (fixed by the reference setup_inputs)
#define S_LEN   16384   // s
#define T_ROWS  8192    // t
#define BATCH   16      // b
#define NH      16      // top-k
#define THREADS 256
#define CAP     512     // candidate buffer per metric (expected ~65 hits)
#define NITER   (S_LEN / 4 / THREADS)   // 16 iterations per thread

typedef unsigned long long u64;
typedef unsigned int u32;

// Output layout: flattened tuple in reference order, all float32
#define OFF_XN    0
#define OFF_IDIST (BATCH * T_ROWS * NH)
#define OFF_ILON  (OFF_IDIST + T_ROWS * NH)
#define OFF_ILAT  (OFF_ILON + T_ROWS * NH)

__global__ __launch_bounds__(THREADS, 8) void nn_topk_kernel(
    const float* __restrict__ x,
    const float* __restrict__ dlon,
    const float* __restrict__ dlat,
    float* __restrict__ out)
{
    __shared__ u64 sbuf[3 * CAP];     // 12 KB candidate buffers
    __shared__ int scnt[3];
    __shared__ u64 sres[3][NH];
    __shared__ u64 sbest;

    const int tid = threadIdx.x;
    const int t   = blockIdx.x;

    if (tid < 3) scnt[tid] = 0;
    __syncthreads();

    const float4* lon4 = reinterpret_cast<const float4*>(dlon + (size_t)t * S_LEN);
    const float4* lat4 = reinterpret_cast<const float4*>(dlat + (size_t)t * S_LEN);

    // Exact push thresholds (same as the passing R7 kernel; bit-pattern compares)
    const u32 TH_ABS = __float_as_uint(0.0050f);  // |lon|, |lat|
    const u32 TH_D2  = __float_as_uint(0.0080f);  // lon^2 + lat^2 (fma form)
    // Branchless filter thresholds: strict supersets of the exact conditions
    // (margin absorbs square/add rounding vs the exact bit compares).
    const float TF_A2 = 2.6e-5f;    // min(lon^2, lat^2)  (0.005^2 = 2.5e-5)
    const float TF_D2 = 0.0082f;    // lon^2 + lat^2 (add form; exact uses fma @0.008)

    // ---- Branchless streaming phase: 2 FSETPs per 4 elements, no pushes ----
    u32 mask = 0;
#pragma unroll 2
    for (int it = 0; it < NITER; ++it) {
        const int i = tid + it * THREADS;
        float4 lo = __ldcs(&lon4[i]);
        float4 la = __ldcs(&lat4[i]);
        float ll0 = lo.x * lo.x, aa0 = la.x * la.x;
        float ll1 = lo.y * lo.y, aa1 = la.y * la.y;
        float ll2 = lo.z * lo.z, aa2 = la.z * la.z;
        float ll3 = lo.w * lo.w, aa3 = la.w * la.w;
        float gmA = fminf(fminf(fminf(ll0, aa0), fminf(ll1, aa1)),
                          fminf(fminf(ll2, aa2), fminf(ll3, aa3)));
        float gmD = fminf(fminf(ll0 + aa0, ll1 + aa1),
                          fminf(ll2 + aa2, ll3 + aa3));
        if (gmA < TF_A2 || gmD < TF_D2) mask |= (1u << it);
    }

    // ---- Cold push epilogue: expected ~0.65 groups per thread ----
    while (mask) {
        const int b = __ffs(mask) - 1;
        mask &= mask - 1;
        const int i = tid + b * THREADS;
        float4 lo = __ldg(&lon4[i]);
        float4 la = __ldg(&lat4[i]);
        float lof[4] = {lo.x, lo.y, lo.z, lo.w};
        float laf[4] = {la.x, la.y, la.z, la.w};
        const int base = i << 2;
#pragma unroll
        for (int j = 0; j < 4; ++j) {
            const u32 abl = __float_as_uint(lof[j]) & 0x7fffffffu;
            const u32 aba = __float_as_uint(laf[j]) & 0x7fffffffu;
            const u32 d2b = __float_as_uint(fmaf(lof[j], lof[j], laf[j] * laf[j]));
            const u32 idx = (u32)(base + j);
            if (d2b < TH_D2) {
                int p = atomicAdd(&scnt[0], 1);
                if (p < CAP) sbuf[0 * CAP + p] = ((u64)d2b << 14) | idx;
            }
            if (abl < TH_ABS) {
                int p = atomicAdd(&scnt[1], 1);
                if (p < CAP) sbuf[1 * CAP + p] = ((u64)abl << 14) | idx;
            }
            if (aba < TH_ABS) {
                int p = atomicAdd(&scnt[2], 1);
                if (p < CAP) sbuf[2 * CAP + p] = ((u64)aba << 14) | idx;
            }
        }
    }
    __syncthreads();

    bool need_fb[3];
#pragma unroll
    for (int m = 0; m < 3; ++m)
        need_fb[m] = (scnt[m] < NH) || (scnt[m] > CAP);

    const int wid  = tid >> 5;
    const int lane = tid & 31;

    // Fast path: warp m extracts the 16 smallest packed keys for metric m.
    // Key = valuebits<<14 | element_index -> ties break by ascending index,
    // exactly like jax.lax.top_k on negated values.
    if (wid < 3 && !need_fb[wid]) {
        const int m = wid;
        const int n = scnt[m];
        for (int r = 0; r < NH; ++r) {
            u64 best = ~0ull;
            for (int p = lane; p < n; p += 32) {
                u64 k = sbuf[m * CAP + p];
                u64 cand = (k << 10) | (u64)p;  // key(46b) << 10 | pos(<=9b)
                if (cand < best) best = cand;
            }
#pragma unroll
            for (int o = 16; o > 0; o >>= 1) {
                u64 other = __shfl_down_sync(0xffffffffu, best, o);
                if (other < best) best = other;
            }
            best = __shfl_sync(0xffffffffu, best, 0);
            if (lane == 0) {
                sres[m][r] = best >> 10;
                sbuf[m * CAP + (int)(best & 1023ull)] = ~0ull;
            }
            __syncwarp();
        }
    }
    __syncthreads();

    // Exact fallback (guaranteed correct; probability ~0 of execution).
    for (int m = 0; m < 3; ++m) {
        if (!need_fb[m]) continue;
        u64 loc[NH];
#pragma unroll
        for (int k = 0; k < NH; ++k) loc[k] = ~0ull;
        const float* a  = dlon + (size_t)t * S_LEN;
        const float* b2 = dlat + (size_t)t * S_LEN;
        for (int i = tid; i < S_LEN; i += THREADS) {
            const float lo = a[i];
            const float la = b2[i];
            u32 bits;
            if (m == 0)      bits = __float_as_uint(fmaf(lo, lo, la * la));
            else if (m == 1) bits = __float_as_uint(lo) & 0x7fffffffu;
            else             bits = __float_as_uint(la) & 0x7fffffffu;
            u64 key = ((u64)bits << 14) | (u32)i;
            if (key < loc[NH - 1]) {
                loc[NH - 1] = key;
#pragma unroll
                for (int k = NH - 1; k > 0; --k) {
                    if (loc[k] < loc[k - 1]) { u64 tmp = loc[k]; loc[k] = loc[k - 1]; loc[k - 1] = tmp; }
                }
            }
        }
        __syncthreads();
        for (int r = 0; r < NH; ++r) {
            if (tid == 0) sbest = ~0ull;
            __syncthreads();
            u64 mymin = ~0ull;
#pragma unroll
            for (int k = 0; k < NH; ++k) mymin = min(mymin, loc[k]);
            atomicMin(&sbest, mymin);
            __syncthreads();
            const u64 bb = sbest;
            if (tid == 0) sres[m][r] = bb;
#pragma unroll
            for (int k = 0; k < NH; ++k)
                if (loc[k] == bb) loc[k] = ~0ull;   // keys unique (contain index)
            __syncthreads();
        }
    }
    __syncthreads();

    // Emit index outputs (as float32)
    if (tid < NH) {
        const int j = tid;
        out[OFF_IDIST + t * NH + j] = (float)(u32)(sres[0][j] & 0x3fffull);
        out[OFF_ILON  + t * NH + j] = (float)(u32)(sres[1][j] & 0x3fffull);
        out[OFF_ILAT  + t * NH + j] = (float)(u32)(sres[2][j] & 0x3fffull);
    }

    // Gather x_nearest: tid = b*NH + j  (BATCH*NH == THREADS)
    {
        const int b = tid >> 4;
        const int j = tid & 15;
        const int idx = (int)(sres[0][j] & 0x3fffull);
        out[OFF_XN + (size_t)b * (T_ROWS * NH) + (size_t)t * NH + j] =
            __ldg(&x[b * S_LEN + idx]);
    }
}

extern "C" void kernel_launch(void* const* d_in, const int* in_sizes, int n_in,
                              void* d_out, int out_size) {
    const float* x    = (const float*)d_in[0];
    const float* dlon = (const float*)d_in[1];
    const float* dlat = (const float*)d_in[2];
    float* out        = (float*)d_out;
    nn_topk_kernel<<<T_ROWS, THREADS>>>(x, dlon, dlat, out);
}